// round 1
// baseline (speedup 1.0000x reference)
#include <cuda_runtime.h>
#include <math.h>

#define B_      1024
#define S_      128
#define E_      512
#define H_      8
#define HD_     64
#define J_      24
#define HJ      192            // H_*J_
#define ROWS_Z  131072         // B_*S_
#define ROWS_J  24576          // B_*J_

// ---------------- scratch (device globals; no allocation allowed) -------------
__device__ float g_q[J_ * E_];                 // 24x512 joint queries projected
__device__ float g_sw[HJ * E_];                // 192x512 fused score weights (already /8)
__device__ float g_sb[HJ];                     // fused score bias (already /8)
__device__ float g_scores[ROWS_Z * HJ];        // 131072x192   (~100 MB)
__device__ float g_V[ROWS_Z * E_];             // 131072x512   (~268 MB)
__device__ float g_o[ROWS_J * E_];             // 24576x512
__device__ float g_jf[ROWS_J * E_];
__device__ float g_h[ROWS_J * E_];

// ---------------- f32x2 helpers (sm_103a packed fp32 pipe) --------------------
__device__ __forceinline__ unsigned long long pk2(float x, float y) {
    unsigned long long r;
    asm("mov.b64 %0, {%1, %2};" : "=l"(r) : "f"(x), "f"(y));
    return r;
}
__device__ __forceinline__ float2 upk2(unsigned long long v) {
    float2 r;
    asm("mov.b64 {%0, %1}, %2;" : "=f"(r.x), "=f"(r.y) : "l"(v));
    return r;
}
#define FMA2(acc, a, b) \
    asm("fma.rn.f32x2 %0, %1, %2, %0;" : "+l"(acc) : "l"(a), "l"(b))

// ---------------- tiny precompute kernels -------------------------------------
// q[j][e] = bq[e] + sum_i jq[j][i] * wq[e][i]
__global__ void k_q(const float* __restrict__ jq, const float* __restrict__ ipw,
                    const float* __restrict__ ipb) {
    int g = blockIdx.x * blockDim.x + threadIdx.x;
    if (g >= J_ * E_) return;
    int j = g / E_, e = g % E_;
    const float4* xq4 = (const float4*)(jq + j * E_);
    const float4* w4  = (const float4*)(ipw + (size_t)e * E_);
    float acc = ipb[e];
    #pragma unroll 4
    for (int i = 0; i < E_ / 4; i++) {
        float4 a = xq4[i], b = w4[i];
        acc += a.x * b.x + a.y * b.y + a.z * b.z + a.w * b.w;
    }
    g_q[j * E_ + e] = acc;
}

// scoreW[h*24+j][e] = (1/8) sum_d q[j][h*64+d] * wk[h*64+d][e];  scoreB likewise with bk
__global__ void k_sw(const float* __restrict__ ipw, const float* __restrict__ ipb) {
    int g = blockIdx.x * blockDim.x + threadIdx.x;
    if (g >= HJ * E_) return;
    int hj = g / E_, e = g % E_;
    int h = hj / J_, j = hj % J_;
    const float* qrow = g_q + j * E_ + h * HD_;
    const float* wk = ipw + (size_t)(E_ + h * HD_) * E_;   // rows 512..1023 of in_proj_w
    float acc = 0.f;
    #pragma unroll 8
    for (int d = 0; d < HD_; d++) acc += qrow[d] * wk[(size_t)d * E_ + e];
    g_sw[hj * E_ + e] = acc * 0.125f;
    if (e == 0) {
        const float* bk = ipb + E_ + h * HD_;
        float bb = 0.f;
        for (int d = 0; d < HD_; d++) bb += qrow[d] * bk[d];
        g_sb[hj] = bb * 0.125f;
    }
}

// ---------------- GEMM: C[M,N] = A[M,K] @ B[N,K]^T + bias[N]  (f32x2 pipe) ----
#define BM 128
#define BN 64
#define BK 16
__global__ __launch_bounds__(128) void k_gemm(
    const float* __restrict__ A, const float* __restrict__ Bm,
    const float* __restrict__ bias, float* __restrict__ C,
    int M, int N, int K) {
    __shared__ float As[BK][BM + 4];   // row = 132 floats = 528B (16B multiple)
    __shared__ float Bs[BK][BN + 4];   // row = 68 floats  = 272B (16B multiple)
    int tid = threadIdx.x;
    int bn = blockIdx.x * BN;          // N-major grid: consecutive blocks reuse same A tile
    int bm = blockIdx.y * BM;
    int tr = (tid >> 3) << 3;          // 0..120
    int tc = (tid & 7) << 3;           // 0..56

    unsigned long long acc2[8][4];
    #pragma unroll
    for (int i = 0; i < 8; i++)
        #pragma unroll
        for (int j = 0; j < 4; j++) acc2[i][j] = 0ull;

    const float4* Ag = (const float4*)(A + (size_t)(bm + tid) * K);
    int bnrow = tid >> 1;
    int bf0 = (tid & 1) * 2;
    const float4* Bg = (const float4*)(Bm + (size_t)(bn + bnrow) * K);

    for (int k0 = 0; k0 < K; k0 += BK) {
        int kb = k0 >> 2;
        #pragma unroll
        for (int i = 0; i < 4; i++) {
            float4 v = Ag[kb + i];
            As[i * 4 + 0][tid] = v.x; As[i * 4 + 1][tid] = v.y;
            As[i * 4 + 2][tid] = v.z; As[i * 4 + 3][tid] = v.w;
        }
        #pragma unroll
        for (int i = 0; i < 2; i++) {
            float4 v = Bg[kb + bf0 + i];
            int kk = (bf0 + i) * 4;
            Bs[kk + 0][bnrow] = v.x; Bs[kk + 1][bnrow] = v.y;
            Bs[kk + 2][bnrow] = v.z; Bs[kk + 3][bnrow] = v.w;
        }
        __syncthreads();
        #pragma unroll
        for (int kk = 0; kk < BK; kk++) {
            float ra[8];
            *(float4*)&ra[0] = *(const float4*)&As[kk][tr];
            *(float4*)&ra[4] = *(const float4*)&As[kk][tr + 4];
            unsigned long long rb[4];
            const unsigned long long* bp = (const unsigned long long*)&Bs[kk][tc];
            rb[0] = bp[0]; rb[1] = bp[1]; rb[2] = bp[2]; rb[3] = bp[3];
            #pragma unroll
            for (int i = 0; i < 8; i++) {
                unsigned long long a2 = pk2(ra[i], ra[i]);
                #pragma unroll
                for (int j = 0; j < 4; j++) FMA2(acc2[i][j], a2, rb[j]);
            }
        }
        __syncthreads();
    }
    #pragma unroll
    for (int i = 0; i < 8; i++) {
        float* Cr = C + (size_t)(bm + tr + i) * N + bn + tc;
        #pragma unroll
        for (int j = 0; j < 4; j++) {
            float2 p = upk2(acc2[i][j]);
            p.x += bias[bn + tc + 2 * j];
            p.y += bias[bn + tc + 2 * j + 1];
            *(float2*)&Cr[2 * j] = p;
        }
    }
}

// ---------------- attention: softmax over s + o = attn @ v --------------------
// one block per (b,h); scores layout [b*S+s][h*24+j]; V layout [b*S+s][h*64+d]
__global__ __launch_bounds__(256) void k_attn() {
    int b = blockIdx.x, h = blockIdx.y;
    __shared__ float sc[J_][130];   // row = 520B (8B multiple)
    __shared__ float Vs[HD_][130];
    int tid = threadIdx.x;

    const float* srow = g_scores + (size_t)b * S_ * HJ + h * J_;
    for (int idx = tid; idx < S_ * J_; idx += 256) {
        int s = idx / J_, j = idx % J_;
        sc[j][s] = srow[(size_t)s * HJ + j];
    }
    __syncthreads();

    int lane = tid & 31, warp = tid >> 5;
    for (int j = warp; j < J_; j += 8) {
        float m = -1e30f;
        for (int s = lane; s < S_; s += 32) m = fmaxf(m, sc[j][s]);
        #pragma unroll
        for (int o = 16; o; o >>= 1) m = fmaxf(m, __shfl_xor_sync(~0u, m, o));
        float sum = 0.f;
        for (int s = lane; s < S_; s += 32) {
            float e = __expf(sc[j][s] - m);
            sc[j][s] = e; sum += e;
        }
        #pragma unroll
        for (int o = 16; o; o >>= 1) sum += __shfl_xor_sync(~0u, sum, o);
        float inv = 1.f / sum;
        for (int s = lane; s < S_; s += 32) sc[j][s] *= inv;
    }

    const float* vrow = g_V + (size_t)b * S_ * E_ + h * HD_;
    for (int idx = tid; idx < S_ * HD_; idx += 256) {
        int s = idx >> 6, d = idx & 63;
        Vs[d][s] = vrow[(size_t)s * E_ + d];   // transpose so s is contiguous
    }
    __syncthreads();

    int d = tid & 63, jb = tid >> 6;           // jb in 0..3, 6 j's per thread
    unsigned long long acc2[6];
    #pragma unroll
    for (int t = 0; t < 6; t++) acc2[t] = 0ull;
    const unsigned long long* vp = (const unsigned long long*)&Vs[d][0];
    for (int s4 = 0; s4 < S_ / 4; s4++) {
        unsigned long long v01 = vp[s4 * 2], v23 = vp[s4 * 2 + 1];
        #pragma unroll
        for (int t = 0; t < 6; t++) {
            const unsigned long long* sp = (const unsigned long long*)&sc[jb * 6 + t][0];
            FMA2(acc2[t], sp[s4 * 2], v01);
            FMA2(acc2[t], sp[s4 * 2 + 1], v23);
        }
    }
    float* obase = g_o + (size_t)b * J_ * E_ + h * HD_ + d;
    #pragma unroll
    for (int t = 0; t < 6; t++) {
        float2 p = upk2(acc2[t]);
        obase[(size_t)(jb * 6 + t) * E_] = p.x + p.y;
    }
}

// ---------------- layernorm + silu (in place on g_h) --------------------------
__global__ __launch_bounds__(256) void k_ln(const float* __restrict__ gam,
                                            const float* __restrict__ bet) {
    int row = blockIdx.x;
    float* hp = g_h + (size_t)row * E_;
    int tid = threadIdx.x;
    float x0 = hp[tid], x1 = hp[tid + 256];
    float s = x0 + x1, s2 = x0 * x0 + x1 * x1;
    #pragma unroll
    for (int o = 16; o; o >>= 1) {
        s  += __shfl_xor_sync(~0u, s, o);
        s2 += __shfl_xor_sync(~0u, s2, o);
    }
    __shared__ float ws[8], ws2[8];
    int warp = tid >> 5, lane = tid & 31;
    if (lane == 0) { ws[warp] = s; ws2[warp] = s2; }
    __syncthreads();
    float S = 0.f, S2 = 0.f;
    #pragma unroll
    for (int i = 0; i < 8; i++) { S += ws[i]; S2 += ws2[i]; }
    float mu = S * (1.f / E_);
    float var = S2 * (1.f / E_) - mu * mu;
    float r = rsqrtf(var + 1e-5f);
    float y0 = (x0 - mu) * r * gam[tid] + bet[tid];
    float y1 = (x1 - mu) * r * gam[tid + 256] + bet[tid + 256];
    hp[tid]       = y0 / (1.f + __expf(-y0));
    hp[tid + 256] = y1 / (1.f + __expf(-y1));
}

// ---------------- head: raw = h @ w2^T + b2; dir/length/offsets ---------------
// one warp per (b,j); writes offsets + length into d_out
__global__ __launch_bounds__(256) void k_head(const float* __restrict__ w2,
                                              const float* __restrict__ b2,
                                              float* __restrict__ out) {
    int w = blockIdx.x * 8 + (threadIdx.x >> 5);   // 0..24575 = b*24+j
    int lane = threadIdx.x & 31;
    int b = w / J_, j = w % J_;
    const float* hp = g_h + (size_t)w * E_;
    float p0 = 0, p1 = 0, p2 = 0, p3 = 0;
    for (int i = lane; i < E_; i += 32) {
        float x = hp[i];
        p0 += x * w2[i];
        p1 += x * w2[E_ + i];
        p2 += x * w2[2 * E_ + i];
        p3 += x * w2[3 * E_ + i];
    }
    #pragma unroll
    for (int o = 16; o; o >>= 1) {
        p0 += __shfl_xor_sync(~0u, p0, o);
        p1 += __shfl_xor_sync(~0u, p1, o);
        p2 += __shfl_xor_sync(~0u, p2, o);
        p3 += __shfl_xor_sync(~0u, p3, o);
    }
    if (lane == 0) {
        float* offp = out + 73728 + (size_t)w * 3;
        if (j == 0) {
            offp[0] = 0.f; offp[1] = 0.f; offp[2] = 0.f;
        } else {
            float dx = p0 + b2[0], dy = p1 + b2[1], dz = p2 + b2[2], lr = p3 + b2[3];
            float n = sqrtf(dx * dx + dy * dy + dz * dz);
            float dn = fmaxf(n, 1e-6f);
            float L = (lr > 0.f) ? (lr + log1pf(expf(-lr))) : log1pf(expf(lr));
            offp[0] = dx / dn * L;
            offp[1] = dy / dn * L;
            offp[2] = dz / dn * L;
            out[147456 + b * 23 + (j - 1)] = L;
        }
    }
}

// ---------------- forward kinematics: joints along parent chain ---------------
__global__ void k_fk(const int* __restrict__ parent, float* __restrict__ out) {
    int g = blockIdx.x * blockDim.x + threadIdx.x;
    if (g >= B_ * 3) return;
    int b = g / 3, c = g % 3;
    const float* off = out + 73728 + (size_t)b * J_ * 3 + c;
    float jp[J_];
    for (int j = 0; j < J_; j++) {
        float v = off[j * 3];
        if (j > 0) v += jp[parent[j]];
        jp[j] = v;
        out[(size_t)b * J_ * 3 + j * 3 + c] = v;
    }
}

// ---------------- launch ------------------------------------------------------
extern "C" void kernel_launch(void* const* d_in, const int* in_sizes, int n_in,
                              void* d_out, int out_size) {
    const float* z   = (const float*)d_in[0];
    const float* jq  = (const float*)d_in[1];
    const float* ipw = (const float*)d_in[2];
    const float* ipb = (const float*)d_in[3];
    const float* opw = (const float*)d_in[4];
    const float* opb = (const float*)d_in[5];
    const float* w1  = (const float*)d_in[6];
    const float* b1  = (const float*)d_in[7];
    const float* lng = (const float*)d_in[8];
    const float* lnb = (const float*)d_in[9];
    const float* w2  = (const float*)d_in[10];
    const float* b2  = (const float*)d_in[11];
    const int*   par = (const int*)d_in[12];
    float* out = (float*)d_out;

    float *p_sw, *p_sb, *p_scores, *p_V, *p_o, *p_jf, *p_h;
    cudaGetSymbolAddress((void**)&p_sw, g_sw);
    cudaGetSymbolAddress((void**)&p_sb, g_sb);
    cudaGetSymbolAddress((void**)&p_scores, g_scores);
    cudaGetSymbolAddress((void**)&p_V, g_V);
    cudaGetSymbolAddress((void**)&p_o, g_o);
    cudaGetSymbolAddress((void**)&p_jf, g_jf);
    cudaGetSymbolAddress((void**)&p_h, g_h);

    // 1) constant precompute: q, fused score weights (K projection eliminated)
    k_q<<<(J_ * E_ + 255) / 256, 256>>>(jq, ipw, ipb);
    k_sw<<<(HJ * E_ + 255) / 256, 256>>>(ipw, ipb);
    // 2) scores = z @ scoreW^T + scoreB   (131072 x 192, pre-scaled by 1/8)
    k_gemm<<<dim3(HJ / BN, ROWS_Z / BM), 128>>>(z, p_sw, p_sb, p_scores,
                                                ROWS_Z, HJ, E_);
    // 3) V = z @ wv^T + bv                (131072 x 512)
    k_gemm<<<dim3(E_ / BN, ROWS_Z / BM), 128>>>(z, ipw + (size_t)2 * E_ * E_,
                                                ipb + 2 * E_, p_V,
                                                ROWS_Z, E_, E_);
    // 4) softmax + o = attn @ v
    k_attn<<<dim3(B_, H_), 256>>>();
    // 5) joint_features = o @ out_proj^T + bo
    k_gemm<<<dim3(E_ / BN, ROWS_J / BM), 128>>>(p_o, opw, opb, p_jf,
                                                ROWS_J, E_, E_);
    // 6) h = jf @ w1^T + b1
    k_gemm<<<dim3(E_ / BN, ROWS_J / BM), 128>>>(p_jf, w1, b1, p_h,
                                                ROWS_J, E_, E_);
    // 7) layernorm + silu (in place)
    k_ln<<<ROWS_J, 256>>>(lng, lnb);
    // 8) head projection + direction/length/offsets
    k_head<<<ROWS_J / 8, 256>>>(w2, b2, out);
    // 9) forward kinematics -> joints
    k_fk<<<(B_ * 3 + 255) / 256, 256>>>(par, out);
}

// round 3
// speedup vs baseline: 1.6108x; 1.6108x over previous
#include <cuda_runtime.h>
#include <cuda_bf16.h>
#include <math.h>
#include <stdint.h>

#define B_      1024
#define S_      128
#define E_      512
#define H_      8
#define HD_     64
#define J_      24
#define HJ      192
#define ROWS_Z  131072
#define ROWS_J  24576
#define NPAD    256

// ---------------- scratch ------------------------------------------------------
__device__ float g_q[J_ * E_];
__device__ float g_sw[NPAD * E_];
__device__ float g_sb[NPAD];
__device__ float g_scores[ROWS_Z * HJ];
__device__ float g_V[ROWS_Z * E_];
__device__ float g_o[ROWS_J * E_];
__device__ float g_jf[ROWS_J * E_];
__device__ float g_h[ROWS_J * E_];

// ---------------- f32x2 helpers (attention) -----------------------------------
__device__ __forceinline__ float2 upk2(unsigned long long v) {
    float2 r;
    asm("mov.b64 {%0, %1}, %2;" : "=f"(r.x), "=f"(r.y) : "l"(v));
    return r;
}
#define FMA2(acc, a, b) \
    asm("fma.rn.f32x2 %0, %1, %2, %0;" : "+l"(acc) : "l"(a), "l"(b))

// ---------------- mma helpers (non-"a" instructions only) ----------------------
__device__ __forceinline__ uint32_t s2u(const void* p) {
    uint32_t a;
    asm("{ .reg .u64 t; cvta.to.shared.u64 t, %1; cvt.u32.u64 %0, t; }" : "=r"(a) : "l"(p));
    return a;
}
// split 2 floats -> packed bf16 hi pair (lo half = first arg) + bf16 lo pair
__device__ __forceinline__ void bfsplit2(float a, float b, uint32_t& hi, uint32_t& lo) {
    asm("cvt.rn.bf16x2.f32 %0, %1, %2;" : "=r"(hi) : "f"(b), "f"(a));
    float ha = __uint_as_float(hi << 16);
    float hb = __uint_as_float(hi & 0xFFFF0000u);
    asm("cvt.rn.bf16x2.f32 %0, %1, %2;" : "=r"(lo) : "f"(b - hb), "f"(a - ha));
}
__device__ __forceinline__ void sts128(uint32_t a, uint32_t x, uint32_t y, uint32_t z, uint32_t w) {
    asm volatile("st.shared.v4.b32 [%0], {%1,%2,%3,%4};" :: "r"(a), "r"(x), "r"(y), "r"(z), "r"(w) : "memory");
}
#define LDSM4(r0, r1, r2, r3, addr) \
    asm volatile("ldmatrix.sync.aligned.m8n8.x4.shared.b16 {%0,%1,%2,%3}, [%4];" \
        : "=r"(r0), "=r"(r1), "=r"(r2), "=r"(r3) : "r"(addr))
#define MMA16816(d, a0, a1, a2, a3, b0, b1) \
    asm volatile("mma.sync.aligned.m16n8k16.row.col.f32.bf16.bf16.f32 " \
        "{%0,%1,%2,%3}, {%4,%5,%6,%7}, {%8,%9}, {%0,%1,%2,%3};" \
        : "+f"((d)[0]), "+f"((d)[1]), "+f"((d)[2]), "+f"((d)[3]) \
        : "r"(a0), "r"(a1), "r"(a2), "r"(a3), "r"(b0), "r"(b1))

// ---------------- tiny precompute kernels --------------------------------------
__global__ void k_q(const float* __restrict__ jq, const float* __restrict__ ipw,
                    const float* __restrict__ ipb) {
    int g = blockIdx.x * blockDim.x + threadIdx.x;
    if (g >= J_ * E_) return;
    int j = g / E_, e = g % E_;
    const float4* xq4 = (const float4*)(jq + j * E_);
    const float4* w4  = (const float4*)(ipw + (size_t)e * E_);
    float acc = ipb[e];
    #pragma unroll 4
    for (int i = 0; i < E_ / 4; i++) {
        float4 a = xq4[i], b = w4[i];
        acc += a.x * b.x + a.y * b.y + a.z * b.z + a.w * b.w;
    }
    g_q[j * E_ + e] = acc;
}

__global__ void k_sw(const float* __restrict__ ipw, const float* __restrict__ ipb) {
    int g = blockIdx.x * blockDim.x + threadIdx.x;
    if (g >= NPAD * E_) return;
    int hj = g / E_, e = g % E_;
    if (hj >= HJ) {
        g_sw[g] = 0.f;
        if (e == 0) g_sb[hj] = 0.f;
        return;
    }
    int h = hj / J_, j = hj % J_;
    const float* qrow = g_q + j * E_ + h * HD_;
    const float* wk = ipw + (size_t)(E_ + h * HD_) * E_;
    float acc = 0.f;
    #pragma unroll 8
    for (int d = 0; d < HD_; d++) acc += qrow[d] * wk[(size_t)d * E_ + e];
    g_sw[hj * E_ + e] = acc * 0.125f;
    if (e == 0) {
        const float* bk = ipb + E_ + h * HD_;
        float bb = 0.f;
        for (int d = 0; d < HD_; d++) bb += qrow[d] * bk[d];
        g_sb[hj] = bb * 0.125f;
    }
}

// ---------------- HMMA GEMM: C[M,N] = A[M,512] @ B[N,512]^T + bias ------------
// fp32 in/out; bf16 hi/lo 3-term split; mma.sync m16n8k16; fp32 accum.
// CTA 128x128, 8 warps of 64x32, K-chunk 16, swizzled smem, reg prefetch.
__global__ __launch_bounds__(256, 1) void k_gemm_mma(
    const float* __restrict__ A, const float* __restrict__ B,
    const float* __restrict__ bias, float* __restrict__ C,
    int ldc, int Nreal) {
    // per row (64B): [hi k0-7 |16B| hi k8-15 | lo k0-7 | lo k8-15], chunks XOR-swizzled
    __shared__ __align__(1024) char sm[16384];   // A tile 8KB, B tile 8KB
    uint32_t sA = s2u(sm), sB = sA + 8192;
    int tid = threadIdx.x;
    int bm = blockIdx.y * 128, bn = blockIdx.x * 128;

    int row = tid >> 1, seg = tid & 1;           // each thread: 8 floats of A + 8 of B per chunk
    const float4* Ag = (const float4*)(A + (size_t)(bm + row) * 512 + seg * 8);
    const float4* Bg = (const float4*)(B + (size_t)(bn + row) * 512 + seg * 8);
    uint32_t rsw = (uint32_t)((row >> 1) & 3);
    uint32_t stAh = sA + row * 64 + ((((uint32_t)seg)     ^ rsw) << 4);
    uint32_t stAl = sA + row * 64 + ((((uint32_t)seg + 2) ^ rsw) << 4);
    uint32_t stBh = sB + row * 64 + ((((uint32_t)seg)     ^ rsw) << 4);
    uint32_t stBl = sB + row * 64 + ((((uint32_t)seg + 2) ^ rsw) << 4);

    int lane = tid & 31, wid = tid >> 5;
    int warpM = wid >> 2, warpN = wid & 3;       // 2x4 warps -> 64x32 each
    // ldmatrix source addresses (lane-dependent)
    uint32_t adAh[4], adAl[4], adBh[2], adBl[2];
    {
        uint32_t kc = (uint32_t)(lane >> 4);     // 0/1
        #pragma unroll
        for (int mt = 0; mt < 4; mt++) {
            uint32_t r = warpM * 64 + mt * 16 + (lane & 15);
            uint32_t rs = (r >> 1) & 3;
            adAh[mt] = sA + r * 64 + (((kc)     ^ rs) << 4);
            adAl[mt] = sA + r * 64 + (((kc + 2) ^ rs) << 4);
        }
        #pragma unroll
        for (int nt = 0; nt < 2; nt++) {
            uint32_t r = warpN * 32 + nt * 16 + (lane & 15);
            uint32_t rs = (r >> 1) & 3;
            adBh[nt] = sB + r * 64 + (((kc)     ^ rs) << 4);
            adBl[nt] = sB + r * 64 + (((kc + 2) ^ rs) << 4);
        }
    }

    float acc[4][4][4];
    #pragma unroll
    for (int i = 0; i < 4; i++)
        #pragma unroll
        for (int j = 0; j < 4; j++)
            #pragma unroll
            for (int k = 0; k < 4; k++) acc[i][j][k] = 0.f;

    float4 pA0 = Ag[0], pA1 = Ag[1], pB0 = Bg[0], pB1 = Bg[1];

    for (int c = 0; c < 32; c++) {
        // split + store this chunk
        uint32_t h0, l0, h1, l1, h2, l2, h3, l3;
        bfsplit2(pA0.x, pA0.y, h0, l0); bfsplit2(pA0.z, pA0.w, h1, l1);
        bfsplit2(pA1.x, pA1.y, h2, l2); bfsplit2(pA1.z, pA1.w, h3, l3);
        sts128(stAh, h0, h1, h2, h3);
        sts128(stAl, l0, l1, l2, l3);
        bfsplit2(pB0.x, pB0.y, h0, l0); bfsplit2(pB0.z, pB0.w, h1, l1);
        bfsplit2(pB1.x, pB1.y, h2, l2); bfsplit2(pB1.z, pB1.w, h3, l3);
        sts128(stBh, h0, h1, h2, h3);
        sts128(stBl, l0, l1, l2, l3);
        __syncthreads();
        if (c < 31) {                            // prefetch next chunk (overlaps MMA)
            pA0 = Ag[(c + 1) * 4]; pA1 = Ag[(c + 1) * 4 + 1];
            pB0 = Bg[(c + 1) * 4]; pB1 = Bg[(c + 1) * 4 + 1];
        }
        // fragments
        uint32_t ah[4][4], al[4][4], bf[2][4];
        #pragma unroll
        for (int mt = 0; mt < 4; mt++) LDSM4(ah[mt][0], ah[mt][1], ah[mt][2], ah[mt][3], adAh[mt]);
        #pragma unroll
        for (int nt = 0; nt < 2; nt++) LDSM4(bf[nt][0], bf[nt][1], bf[nt][2], bf[nt][3], adBh[nt]);
        // hh
        #pragma unroll
        for (int mt = 0; mt < 4; mt++)
            #pragma unroll
            for (int n8 = 0; n8 < 4; n8++)
                MMA16816(acc[mt][n8], ah[mt][0], ah[mt][1], ah[mt][2], ah[mt][3],
                         bf[n8 >> 1][n8 & 1], bf[n8 >> 1][2 + (n8 & 1)]);
        // lh (A-lo x B-hi)
        #pragma unroll
        for (int mt = 0; mt < 4; mt++) LDSM4(al[mt][0], al[mt][1], al[mt][2], al[mt][3], adAl[mt]);
        #pragma unroll
        for (int mt = 0; mt < 4; mt++)
            #pragma unroll
            for (int n8 = 0; n8 < 4; n8++)
                MMA16816(acc[mt][n8], al[mt][0], al[mt][1], al[mt][2], al[mt][3],
                         bf[n8 >> 1][n8 & 1], bf[n8 >> 1][2 + (n8 & 1)]);
        // hl (A-hi x B-lo)
        #pragma unroll
        for (int nt = 0; nt < 2; nt++) LDSM4(bf[nt][0], bf[nt][1], bf[nt][2], bf[nt][3], adBl[nt]);
        #pragma unroll
        for (int mt = 0; mt < 4; mt++)
            #pragma unroll
            for (int n8 = 0; n8 < 4; n8++)
                MMA16816(acc[mt][n8], ah[mt][0], ah[mt][1], ah[mt][2], ah[mt][3],
                         bf[n8 >> 1][n8 & 1], bf[n8 >> 1][2 + (n8 & 1)]);
        __syncthreads();
    }

    // epilogue
    int lr = lane >> 2, lc = (lane & 3) * 2;
    #pragma unroll
    for (int mt = 0; mt < 4; mt++) {
        int r0 = bm + warpM * 64 + mt * 16 + lr;
        #pragma unroll
        for (int n8 = 0; n8 < 4; n8++) {
            int col = bn + warpN * 32 + n8 * 8 + lc;
            if (col < Nreal) {
                float bx = __ldg(bias + col), by = __ldg(bias + col + 1);
                float2 v0 = make_float2(acc[mt][n8][0] + bx, acc[mt][n8][1] + by);
                float2 v1 = make_float2(acc[mt][n8][2] + bx, acc[mt][n8][3] + by);
                *(float2*)(C + (size_t)r0 * ldc + col) = v0;
                *(float2*)(C + (size_t)(r0 + 8) * ldc + col) = v1;
            }
        }
    }
}

// ---------------- attention ----------------------------------------------------
__global__ __launch_bounds__(256) void k_attn() {
    int b = blockIdx.x, h = blockIdx.y;
    __shared__ float sc[J_][130];
    __shared__ float Vs[HD_][130];
    int tid = threadIdx.x;

    const float* srow = g_scores + (size_t)b * S_ * HJ + h * J_;
    for (int idx = tid; idx < S_ * J_; idx += 256) {
        int s = idx / J_, j = idx % J_;
        sc[j][s] = srow[(size_t)s * HJ + j];
    }
    __syncthreads();

    int lane = tid & 31, warp = tid >> 5;
    for (int j = warp; j < J_; j += 8) {
        float m = -1e30f;
        for (int s = lane; s < S_; s += 32) m = fmaxf(m, sc[j][s]);
        #pragma unroll
        for (int o = 16; o; o >>= 1) m = fmaxf(m, __shfl_xor_sync(~0u, m, o));
        float sum = 0.f;
        for (int s = lane; s < S_; s += 32) {
            float e = __expf(sc[j][s] - m);
            sc[j][s] = e; sum += e;
        }
        #pragma unroll
        for (int o = 16; o; o >>= 1) sum += __shfl_xor_sync(~0u, sum, o);
        float inv = 1.f / sum;
        for (int s = lane; s < S_; s += 32) sc[j][s] *= inv;
    }

    const float* vrow = g_V + (size_t)b * S_ * E_ + h * HD_;
    for (int idx = tid; idx < S_ * HD_; idx += 256) {
        int s = idx >> 6, d = idx & 63;
        Vs[d][s] = vrow[(size_t)s * E_ + d];
    }
    __syncthreads();

    int d = tid & 63, jb = tid >> 6;
    unsigned long long acc2[6];
    #pragma unroll
    for (int t = 0; t < 6; t++) acc2[t] = 0ull;
    const unsigned long long* vp = (const unsigned long long*)&Vs[d][0];
    for (int s4 = 0; s4 < S_ / 4; s4++) {
        unsigned long long v01 = vp[s4 * 2], v23 = vp[s4 * 2 + 1];
        #pragma unroll
        for (int t = 0; t < 6; t++) {
            const unsigned long long* sp = (const unsigned long long*)&sc[jb * 6 + t][0];
            FMA2(acc2[t], sp[s4 * 2], v01);
            FMA2(acc2[t], sp[s4 * 2 + 1], v23);
        }
    }
    float* obase = g_o + (size_t)b * J_ * E_ + h * HD_ + d;
    #pragma unroll
    for (int t = 0; t < 6; t++) {
        float2 p = upk2(acc2[t]);
        obase[(size_t)(jb * 6 + t) * E_] = p.x + p.y;
    }
}

// ---------------- layernorm + silu ---------------------------------------------
__global__ __launch_bounds__(256) void k_ln(const float* __restrict__ gam,
                                            const float* __restrict__ bet) {
    int row = blockIdx.x;
    float* hp = g_h + (size_t)row * E_;
    int tid = threadIdx.x;
    float x0 = hp[tid], x1 = hp[tid + 256];
    float s = x0 + x1, s2 = x0 * x0 + x1 * x1;
    #pragma unroll
    for (int o = 16; o; o >>= 1) {
        s  += __shfl_xor_sync(~0u, s, o);
        s2 += __shfl_xor_sync(~0u, s2, o);
    }
    __shared__ float ws[8], ws2[8];
    int warp = tid >> 5, lane = tid & 31;
    if (lane == 0) { ws[warp] = s; ws2[warp] = s2; }
    __syncthreads();
    float S = 0.f, S2 = 0.f;
    #pragma unroll
    for (int i = 0; i < 8; i++) { S += ws[i]; S2 += ws2[i]; }
    float mu = S * (1.f / E_);
    float var = S2 * (1.f / E_) - mu * mu;
    float r = rsqrtf(var + 1e-5f);
    float y0 = (x0 - mu) * r * gam[tid] + bet[tid];
    float y1 = (x1 - mu) * r * gam[tid + 256] + bet[tid + 256];
    hp[tid]       = y0 / (1.f + __expf(-y0));
    hp[tid + 256] = y1 / (1.f + __expf(-y1));
}

// ---------------- head + offsets -----------------------------------------------
__global__ __launch_bounds__(256) void k_head(const float* __restrict__ w2,
                                              const float* __restrict__ b2,
                                              float* __restrict__ out) {
    int w = blockIdx.x * 8 + (threadIdx.x >> 5);
    int lane = threadIdx.x & 31;
    int b = w / J_, j = w % J_;
    const float* hp = g_h + (size_t)w * E_;
    float p0 = 0, p1 = 0, p2 = 0, p3 = 0;
    for (int i = lane; i < E_; i += 32) {
        float x = hp[i];
        p0 += x * w2[i];
        p1 += x * w2[E_ + i];
        p2 += x * w2[2 * E_ + i];
        p3 += x * w2[3 * E_ + i];
    }
    #pragma unroll
    for (int o = 16; o; o >>= 1) {
        p0 += __shfl_xor_sync(~0u, p0, o);
        p1 += __shfl_xor_sync(~0u, p1, o);
        p2 += __shfl_xor_sync(~0u, p2, o);
        p3 += __shfl_xor_sync(~0u, p3, o);
    }
    if (lane == 0) {
        float* offp = out + 73728 + (size_t)w * 3;
        if (j == 0) {
            offp[0] = 0.f; offp[1] = 0.f; offp[2] = 0.f;
        } else {
            float dx = p0 + b2[0], dy = p1 + b2[1], dz = p2 + b2[2], lr = p3 + b2[3];
            float n = sqrtf(dx * dx + dy * dy + dz * dz);
            float dn = fmaxf(n, 1e-6f);
            float L = (lr > 0.f) ? (lr + log1pf(expf(-lr))) : log1pf(expf(lr));
            offp[0] = dx / dn * L;
            offp[1] = dy / dn * L;
            offp[2] = dz / dn * L;
            out[147456 + b * 23 + (j - 1)] = L;
        }
    }
}

// ---------------- forward kinematics -------------------------------------------
__global__ void k_fk(const int* __restrict__ parent, float* __restrict__ out) {
    int g = blockIdx.x * blockDim.x + threadIdx.x;
    if (g >= B_ * 3) return;
    int b = g / 3, c = g % 3;
    const float* off = out + 73728 + (size_t)b * J_ * 3 + c;
    float jp[J_];
    for (int j = 0; j < J_; j++) {
        float v = off[j * 3];
        if (j > 0) v += jp[parent[j]];
        jp[j] = v;
        out[(size_t)b * J_ * 3 + j * 3 + c] = v;
    }
}

// ---------------- launch --------------------------------------------------------
extern "C" void kernel_launch(void* const* d_in, const int* in_sizes, int n_in,
                              void* d_out, int out_size) {
    const float* z   = (const float*)d_in[0];
    const float* jq  = (const float*)d_in[1];
    const float* ipw = (const float*)d_in[2];
    const float* ipb = (const float*)d_in[3];
    const float* opw = (const float*)d_in[4];
    const float* opb = (const float*)d_in[5];
    const float* w1  = (const float*)d_in[6];
    const float* b1  = (const float*)d_in[7];
    const float* lng = (const float*)d_in[8];
    const float* lnb = (const float*)d_in[9];
    const float* w2  = (const float*)d_in[10];
    const float* b2  = (const float*)d_in[11];
    const int*   par = (const int*)d_in[12];
    float* out = (float*)d_out;

    float *p_sw, *p_sb, *p_scores, *p_V, *p_o, *p_jf, *p_h;
    cudaGetSymbolAddress((void**)&p_sw, g_sw);
    cudaGetSymbolAddress((void**)&p_sb, g_sb);
    cudaGetSymbolAddress((void**)&p_scores, g_scores);
    cudaGetSymbolAddress((void**)&p_V, g_V);
    cudaGetSymbolAddress((void**)&p_o, g_o);
    cudaGetSymbolAddress((void**)&p_jf, g_jf);
    cudaGetSymbolAddress((void**)&p_h, g_h);

    // 1) constant precompute (K projection folded away)
    k_q<<<(J_ * E_ + 255) / 256, 256>>>(jq, ipw, ipb);
    k_sw<<<(NPAD * E_ + 255) / 256, 256>>>(ipw, ipb);
    // 2) scores = z @ scoreW^T + scoreB  (131072 x 192, B padded to 256)
    k_gemm_mma<<<dim3(2, ROWS_Z / 128), 256>>>(z, p_sw, p_sb, p_scores, HJ, HJ);
    // 3) V = z @ wv^T + bv               (131072 x 512)
    k_gemm_mma<<<dim3(4, ROWS_Z / 128), 256>>>(z, ipw + (size_t)2 * E_ * E_,
                                               ipb + 2 * E_, p_V, E_, E_);
    // 4) softmax + o = attn @ v
    k_attn<<<dim3(B_, H_), 256>>>();
    // 5) joint_features = o @ out_proj^T + bo
    k_gemm_mma<<<dim3(4, ROWS_J / 128), 256>>>(p_o, opw, opb, p_jf, E_, E_);
    // 6) h = jf @ w1^T + b1
    k_gemm_mma<<<dim3(4, ROWS_J / 128), 256>>>(p_jf, w1, b1, p_h, E_, E_);
    // 7) layernorm + silu
    k_ln<<<ROWS_J, 256>>>(lng, lnb);
    // 8) head projection + offsets
    k_head<<<ROWS_J / 8, 256>>>(w2, b2, out);
    // 9) forward kinematics
    k_fk<<<(B_ * 3 + 255) / 256, 256>>>(par, out);
}

// round 4
// speedup vs baseline: 2.1833x; 1.3554x over previous
#include <cuda_runtime.h>
#include <cuda_bf16.h>
#include <math.h>
#include <stdint.h>

#define B_      1024
#define S_      128
#define E_      512
#define H_      8
#define HD_     64
#define J_      24
#define HJ      192
#define ROWS_Z  131072
#define ROWS_J  24576
#define NPAD    256
#define NCAT    768            // scoreW_pad(256) + wv(512)
#define ST      3              // pipeline stages

// ---------------- scratch ------------------------------------------------------
__device__ float          g_q[J_ * E_];
__device__ float          g_sv[(size_t)ROWS_Z * NCAT];          // scores(0..255) | V(256..767)
__device__ __nv_bfloat16  g_zhi[(size_t)ROWS_Z * E_];
__device__ __nv_bfloat16  g_zlo[(size_t)ROWS_Z * E_];
__device__ __nv_bfloat16  g_bch[NCAT * E_];                     // Bcat hi
__device__ __nv_bfloat16  g_bcl[NCAT * E_];                     // Bcat lo
__device__ float          g_bias[NCAT];
__device__ __nv_bfloat16  g_opwh[E_ * E_], g_opwl[E_ * E_];
__device__ __nv_bfloat16  g_w1h[E_ * E_],  g_w1l[E_ * E_];
__device__ __nv_bfloat16  g_ohi[(size_t)ROWS_J * E_], g_olo[(size_t)ROWS_J * E_];
__device__ __nv_bfloat16  g_jfh[(size_t)ROWS_J * E_], g_jfl[(size_t)ROWS_J * E_];
__device__ float          g_h[(size_t)ROWS_J * E_];

// ---------------- helpers ------------------------------------------------------
__device__ __forceinline__ float2 upk2(unsigned long long v) {
    float2 r;
    asm("mov.b64 {%0, %1}, %2;" : "=f"(r.x), "=f"(r.y) : "l"(v));
    return r;
}
#define FMA2(acc, a, b) \
    asm("fma.rn.f32x2 %0, %1, %2, %0;" : "+l"(acc) : "l"(a), "l"(b))

__device__ __forceinline__ uint32_t s2u(const void* p) {
    uint32_t a;
    asm("{ .reg .u64 t; cvta.to.shared.u64 t, %1; cvt.u32.u64 %0, t; }" : "=r"(a) : "l"(p));
    return a;
}
// split 2 floats -> packed bf16 hi pair (lo half = first arg) + bf16 lo pair
__device__ __forceinline__ void bfsplit2(float a, float b, uint32_t& hi, uint32_t& lo) {
    asm("cvt.rn.bf16x2.f32 %0, %1, %2;" : "=r"(hi) : "f"(b), "f"(a));
    float ha = __uint_as_float(hi << 16);
    float hb = __uint_as_float(hi & 0xFFFF0000u);
    asm("cvt.rn.bf16x2.f32 %0, %1, %2;" : "=r"(lo) : "f"(b - hb), "f"(a - ha));
}
#define CPA(dst, src) \
    asm volatile("cp.async.cg.shared.global [%0], [%1], 16;" :: "r"(dst), "l"(src) : "memory")
#define CP_COMMIT() asm volatile("cp.async.commit_group;" ::: "memory")
#define CP_WAIT1()  asm volatile("cp.async.wait_group 1;" ::: "memory")
#define LDSM4(r0, r1, r2, r3, addr) \
    asm volatile("ldmatrix.sync.aligned.m8n8.x4.shared.b16 {%0,%1,%2,%3}, [%4];" \
        : "=r"(r0), "=r"(r1), "=r"(r2), "=r"(r3) : "r"(addr))
#define MMA16816(d, a0, a1, a2, a3, b0, b1) \
    asm volatile("mma.sync.aligned.m16n8k16.row.col.f32.bf16.bf16.f32 " \
        "{%0,%1,%2,%3}, {%4,%5,%6,%7}, {%8,%9}, {%0,%1,%2,%3};" \
        : "+f"((d)[0]), "+f"((d)[1]), "+f"((d)[2]), "+f"((d)[3]) \
        : "r"(a0), "r"(a1), "r"(a2), "r"(a3), "r"(b0), "r"(b1))

// ---------------- fp32 -> bf16 hi/lo split (bulk) -------------------------------
__global__ void k_split(const float4* __restrict__ src, uint2* __restrict__ hi,
                        uint2* __restrict__ lo, int n4) {
    int g = blockIdx.x * blockDim.x + threadIdx.x;
    if (g >= n4) return;
    float4 v = src[g];
    uint32_t h0, l0, h1, l1;
    bfsplit2(v.x, v.y, h0, l0);
    bfsplit2(v.z, v.w, h1, l1);
    hi[g] = make_uint2(h0, h1);
    lo[g] = make_uint2(l0, l1);
}

// ---------------- precompute: q ------------------------------------------------
__global__ void k_q(const float* __restrict__ jq, const float* __restrict__ ipw,
                    const float* __restrict__ ipb) {
    int g = blockIdx.x * blockDim.x + threadIdx.x;
    if (g >= J_ * E_) return;
    int j = g / E_, e = g % E_;
    const float4* xq4 = (const float4*)(jq + j * E_);
    const float4* w4  = (const float4*)(ipw + (size_t)e * E_);
    float acc = ipb[e];
    #pragma unroll 4
    for (int i = 0; i < E_ / 4; i++) {
        float4 a = xq4[i], b = w4[i];
        acc += a.x * b.x + a.y * b.y + a.z * b.z + a.w * b.w;
    }
    g_q[j * E_ + e] = acc;
}

// ---------------- precompute: fused score weights -> Bcat rows 0..255 ----------
__global__ void k_sw(const float* __restrict__ ipw, const float* __restrict__ ipb) {
    int g = blockIdx.x * blockDim.x + threadIdx.x;
    if (g >= NPAD * E_) return;
    int hj = g / E_, e = g % E_;
    float v = 0.f;
    if (hj < HJ) {
        int h = hj / J_, j = hj % J_;
        const float* qrow = g_q + j * E_ + h * HD_;
        const float* wk = ipw + (size_t)(E_ + h * HD_) * E_;
        float acc = 0.f;
        #pragma unroll 8
        for (int d = 0; d < HD_; d++) acc += qrow[d] * wk[(size_t)d * E_ + e];
        v = acc * 0.125f;
        if (e == 0) {
            const float* bk = ipb + E_ + h * HD_;
            float bb = 0.f;
            for (int d = 0; d < HD_; d++) bb += qrow[d] * bk[d];
            g_bias[hj] = bb * 0.125f;
        }
    } else if (e == 0) {
        g_bias[hj] = 0.f;
    }
    __nv_bfloat16 hb = __float2bfloat16(v);
    g_bch[hj * E_ + e] = hb;
    g_bcl[hj * E_ + e] = __float2bfloat16(v - __bfloat162float(hb));
}

__global__ void k_bcopy(const float* __restrict__ ipb) {
    int i = threadIdx.x + blockIdx.x * blockDim.x;
    if (i < E_) g_bias[NPAD + i] = ipb[2 * E_ + i];
}

// ---------------- pipelined HMMA GEMM ------------------------------------------
// C[M,N] = A[M,512] @ B[N,512]^T + bias ; A,B pre-split bf16 hi/lo.
// CTA 128x128, 8 warps 64x32, K-chunk 32, 3-stage cp.async, one bar/chunk.
__global__ __launch_bounds__(256) void k_gemm_bf(
    const __nv_bfloat16* __restrict__ Ah, const __nv_bfloat16* __restrict__ Al,
    const __nv_bfloat16* __restrict__ Bh, const __nv_bfloat16* __restrict__ Bl,
    const float* __restrict__ bias,
    float* __restrict__ C, __nv_bfloat16* __restrict__ Chi, __nv_bfloat16* __restrict__ Clo,
    int ldc, int writeSplit) {
    extern __shared__ char sm[];             // ST * 32768 bytes
    uint32_t sb = s2u(sm);
    int tid = threadIdx.x;
    int bm = blockIdx.y * 128, bn = blockIdx.x * 128;

    // cp.async mapping: thread -> (row, 2 consecutive 16B segs of a 64B chunk-row)
    int row = tid >> 1, sp = (tid & 1) * 2;
    uint32_t rsw = (uint32_t)((row >> 1) & 3);
    uint32_t d0 = (uint32_t)row * 64 + (((uint32_t)sp ^ rsw) << 4);
    uint32_t d1 = (uint32_t)row * 64 + ((((uint32_t)sp + 1) ^ rsw) << 4);
    const char* gAh = (const char*)(Ah + (size_t)(bm + row) * 512) + sp * 16;
    const char* gAl = (const char*)(Al + (size_t)(bm + row) * 512) + sp * 16;
    const char* gBh = (const char*)(Bh + (size_t)(bn + row) * 512) + sp * 16;
    const char* gBl = (const char*)(Bl + (size_t)(bn + row) * 512) + sp * 16;

    auto issue = [&](int c) {
        uint32_t st = sb + (uint32_t)(c % ST) * 32768u;
        const char* a = gAh + c * 64;
        CPA(st + d0, a); CPA(st + d1, a + 16);
        a = gAl + c * 64;
        CPA(st + 8192 + d0, a); CPA(st + 8192 + d1, a + 16);
        a = gBh + c * 64;
        CPA(st + 16384 + d0, a); CPA(st + 16384 + d1, a + 16);
        a = gBl + c * 64;
        CPA(st + 24576 + d0, a); CPA(st + 24576 + d1, a + 16);
    };

    // ldmatrix per-thread bases
    int lane = tid & 31, wid = tid >> 5;
    int warpM = wid >> 2, warpN = wid & 3;
    uint32_t kc = (uint32_t)(lane >> 4);
    uint32_t offA[4], swA[4], offB[2], swB[2];
    #pragma unroll
    for (int mt = 0; mt < 4; mt++) {
        uint32_t r = warpM * 64 + mt * 16 + (lane & 15);
        offA[mt] = r * 64;  swA[mt] = (r >> 1) & 3;
    }
    #pragma unroll
    for (int nt = 0; nt < 2; nt++) {
        uint32_t r = warpN * 32 + nt * 16 + (lane & 15);
        offB[nt] = r * 64;  swB[nt] = (r >> 1) & 3;
    }

    float acc[4][4][4];
    #pragma unroll
    for (int i = 0; i < 4; i++)
        #pragma unroll
        for (int j = 0; j < 4; j++)
            #pragma unroll
            for (int k = 0; k < 4; k++) acc[i][j][k] = 0.f;

    issue(0); CP_COMMIT();
    issue(1); CP_COMMIT();

    for (int c = 0; c < 16; c++) {
        CP_WAIT1();
        __syncthreads();
        if (c + 2 < 16) issue(c + 2);
        CP_COMMIT();
        uint32_t tb = sb + (uint32_t)(c % ST) * 32768u;
        #pragma unroll
        for (int g = 0; g < 2; g++) {
            uint32_t seg = 2u * g + kc;
            uint32_t ah[4][4], bh[2][4];
            #pragma unroll
            for (int mt = 0; mt < 4; mt++)
                LDSM4(ah[mt][0], ah[mt][1], ah[mt][2], ah[mt][3],
                      tb + offA[mt] + ((seg ^ swA[mt]) << 4));
            #pragma unroll
            for (int nt = 0; nt < 2; nt++)
                LDSM4(bh[nt][0], bh[nt][1], bh[nt][2], bh[nt][3],
                      tb + 16384 + offB[nt] + ((seg ^ swB[nt]) << 4));
            #pragma unroll
            for (int mt = 0; mt < 4; mt++)
                #pragma unroll
                for (int n8 = 0; n8 < 4; n8++)
                    MMA16816(acc[mt][n8], ah[mt][0], ah[mt][1], ah[mt][2], ah[mt][3],
                             bh[n8 >> 1][n8 & 1], bh[n8 >> 1][2 + (n8 & 1)]);
            uint32_t al[4][4];
            #pragma unroll
            for (int mt = 0; mt < 4; mt++)
                LDSM4(al[mt][0], al[mt][1], al[mt][2], al[mt][3],
                      tb + 8192 + offA[mt] + ((seg ^ swA[mt]) << 4));
            #pragma unroll
            for (int mt = 0; mt < 4; mt++)
                #pragma unroll
                for (int n8 = 0; n8 < 4; n8++)
                    MMA16816(acc[mt][n8], al[mt][0], al[mt][1], al[mt][2], al[mt][3],
                             bh[n8 >> 1][n8 & 1], bh[n8 >> 1][2 + (n8 & 1)]);
            uint32_t bl[2][4];
            #pragma unroll
            for (int nt = 0; nt < 2; nt++)
                LDSM4(bl[nt][0], bl[nt][1], bl[nt][2], bl[nt][3],
                      tb + 24576 + offB[nt] + ((seg ^ swB[nt]) << 4));
            #pragma unroll
            for (int mt = 0; mt < 4; mt++)
                #pragma unroll
                for (int n8 = 0; n8 < 4; n8++)
                    MMA16816(acc[mt][n8], ah[mt][0], ah[mt][1], ah[mt][2], ah[mt][3],
                             bl[n8 >> 1][n8 & 1], bl[n8 >> 1][2 + (n8 & 1)]);
        }
    }

    // epilogue
    int lr = lane >> 2, lc = (lane & 3) * 2;
    #pragma unroll
    for (int mt = 0; mt < 4; mt++) {
        int r0 = bm + warpM * 64 + mt * 16 + lr;
        #pragma unroll
        for (int n8 = 0; n8 < 4; n8++) {
            int col = bn + warpN * 32 + n8 * 8 + lc;
            float bx = __ldg(bias + col), by = __ldg(bias + col + 1);
            float v00 = acc[mt][n8][0] + bx, v01 = acc[mt][n8][1] + by;
            float v10 = acc[mt][n8][2] + bx, v11 = acc[mt][n8][3] + by;
            if (!writeSplit) {
                *(float2*)(C + (size_t)r0 * ldc + col) = make_float2(v00, v01);
                *(float2*)(C + (size_t)(r0 + 8) * ldc + col) = make_float2(v10, v11);
            } else {
                uint32_t h, l;
                bfsplit2(v00, v01, h, l);
                *(uint32_t*)((char*)Chi + ((size_t)r0 * ldc + col) * 2) = h;
                *(uint32_t*)((char*)Clo + ((size_t)r0 * ldc + col) * 2) = l;
                bfsplit2(v10, v11, h, l);
                *(uint32_t*)((char*)Chi + ((size_t)(r0 + 8) * ldc + col) * 2) = h;
                *(uint32_t*)((char*)Clo + ((size_t)(r0 + 8) * ldc + col) * 2) = l;
            }
        }
    }
}

// ---------------- attention ----------------------------------------------------
__global__ __launch_bounds__(256) void k_attn() {
    int b = blockIdx.x, h = blockIdx.y;
    __shared__ float sc[J_][130];
    __shared__ float Vs[HD_][130];
    int tid = threadIdx.x;

    const float* srow = g_sv + (size_t)b * S_ * NCAT + h * J_;
    for (int idx = tid; idx < S_ * J_; idx += 256) {
        int s = idx / J_, j = idx % J_;
        sc[j][s] = srow[(size_t)s * NCAT + j];
    }
    __syncthreads();

    int lane = tid & 31, warp = tid >> 5;
    for (int j = warp; j < J_; j += 8) {
        float m = -1e30f;
        for (int s = lane; s < S_; s += 32) m = fmaxf(m, sc[j][s]);
        #pragma unroll
        for (int o = 16; o; o >>= 1) m = fmaxf(m, __shfl_xor_sync(~0u, m, o));
        float sum = 0.f;
        for (int s = lane; s < S_; s += 32) {
            float e = __expf(sc[j][s] - m);
            sc[j][s] = e; sum += e;
        }
        #pragma unroll
        for (int o = 16; o; o >>= 1) sum += __shfl_xor_sync(~0u, sum, o);
        float inv = 1.f / sum;
        for (int s = lane; s < S_; s += 32) sc[j][s] *= inv;
    }

    const float* vrow = g_sv + (size_t)b * S_ * NCAT + NPAD + h * HD_;
    for (int idx = tid; idx < S_ * HD_; idx += 256) {
        int s = idx >> 6, d = idx & 63;
        Vs[d][s] = vrow[(size_t)s * NCAT + d];
    }
    __syncthreads();

    int d = tid & 63, jb = tid >> 6;
    unsigned long long acc2[6];
    #pragma unroll
    for (int t = 0; t < 6; t++) acc2[t] = 0ull;
    const unsigned long long* vp = (const unsigned long long*)&Vs[d][0];
    for (int s4 = 0; s4 < S_ / 4; s4++) {
        unsigned long long v01 = vp[s4 * 2], v23 = vp[s4 * 2 + 1];
        #pragma unroll
        for (int t = 0; t < 6; t++) {
            const unsigned long long* sp = (const unsigned long long*)&sc[jb * 6 + t][0];
            FMA2(acc2[t], sp[s4 * 2], v01);
            FMA2(acc2[t], sp[s4 * 2 + 1], v23);
        }
    }
    size_t obase = (size_t)b * J_ * E_ + h * HD_ + d;
    #pragma unroll
    for (int t = 0; t < 6; t++) {
        float2 p = upk2(acc2[t]);
        float v = p.x + p.y;
        size_t off = obase + (size_t)(jb * 6 + t) * E_;
        __nv_bfloat16 hb = __float2bfloat16(v);
        g_ohi[off] = hb;
        g_olo[off] = __float2bfloat16(v - __bfloat162float(hb));
    }
}

// ---------------- layernorm + silu ---------------------------------------------
__global__ __launch_bounds__(256) void k_ln(const float* __restrict__ gam,
                                            const float* __restrict__ bet) {
    int row = blockIdx.x;
    float* hp = g_h + (size_t)row * E_;
    int tid = threadIdx.x;
    float x0 = hp[tid], x1 = hp[tid + 256];
    float s = x0 + x1, s2 = x0 * x0 + x1 * x1;
    #pragma unroll
    for (int o = 16; o; o >>= 1) {
        s  += __shfl_xor_sync(~0u, s, o);
        s2 += __shfl_xor_sync(~0u, s2, o);
    }
    __shared__ float ws[8], ws2[8];
    int warp = tid >> 5, lane = tid & 31;
    if (lane == 0) { ws[warp] = s; ws2[warp] = s2; }
    __syncthreads();
    float S = 0.f, S2 = 0.f;
    #pragma unroll
    for (int i = 0; i < 8; i++) { S += ws[i]; S2 += ws2[i]; }
    float mu = S * (1.f / E_);
    float var = S2 * (1.f / E_) - mu * mu;
    float r = rsqrtf(var + 1e-5f);
    float y0 = (x0 - mu) * r * gam[tid] + bet[tid];
    float y1 = (x1 - mu) * r * gam[tid + 256] + bet[tid + 256];
    hp[tid]       = y0 / (1.f + __expf(-y0));
    hp[tid + 256] = y1 / (1.f + __expf(-y1));
}

// ---------------- head + offsets -----------------------------------------------
__global__ __launch_bounds__(256) void k_head(const float* __restrict__ w2,
                                              const float* __restrict__ b2,
                                              float* __restrict__ out) {
    int w = blockIdx.x * 8 + (threadIdx.x >> 5);
    int lane = threadIdx.x & 31;
    int b = w / J_, j = w % J_;
    const float* hp = g_h + (size_t)w * E_;
    float p0 = 0, p1 = 0, p2 = 0, p3 = 0;
    for (int i = lane; i < E_; i += 32) {
        float x = hp[i];
        p0 += x * w2[i];
        p1 += x * w2[E_ + i];
        p2 += x * w2[2 * E_ + i];
        p3 += x * w2[3 * E_ + i];
    }
    #pragma unroll
    for (int o = 16; o; o >>= 1) {
        p0 += __shfl_xor_sync(~0u, p0, o);
        p1 += __shfl_xor_sync(~0u, p1, o);
        p2 += __shfl_xor_sync(~0u, p2, o);
        p3 += __shfl_xor_sync(~0u, p3, o);
    }
    if (lane == 0) {
        float* offp = out + 73728 + (size_t)w * 3;
        if (j == 0) {
            offp[0] = 0.f; offp[1] = 0.f; offp[2] = 0.f;
        } else {
            float dx = p0 + b2[0], dy = p1 + b2[1], dz = p2 + b2[2], lr = p3 + b2[3];
            float n = sqrtf(dx * dx + dy * dy + dz * dz);
            float dn = fmaxf(n, 1e-6f);
            float L = (lr > 0.f) ? (lr + log1pf(expf(-lr))) : log1pf(expf(lr));
            offp[0] = dx / dn * L;
            offp[1] = dy / dn * L;
            offp[2] = dz / dn * L;
            out[147456 + b * 23 + (j - 1)] = L;
        }
    }
}

// ---------------- forward kinematics -------------------------------------------
__global__ void k_fk(const int* __restrict__ parent, float* __restrict__ out) {
    int g = blockIdx.x * blockDim.x + threadIdx.x;
    if (g >= B_ * 3) return;
    int b = g / 3, c = g % 3;
    const float* off = out + 73728 + (size_t)b * J_ * 3 + c;
    float jp[J_];
    for (int j = 0; j < J_; j++) {
        float v = off[j * 3];
        if (j > 0) v += jp[parent[j]];
        jp[j] = v;
        out[(size_t)b * J_ * 3 + j * 3 + c] = v;
    }
}

// ---------------- launch --------------------------------------------------------
extern "C" void kernel_launch(void* const* d_in, const int* in_sizes, int n_in,
                              void* d_out, int out_size) {
    const float* z   = (const float*)d_in[0];
    const float* jq  = (const float*)d_in[1];
    const float* ipw = (const float*)d_in[2];
    const float* ipb = (const float*)d_in[3];
    const float* opw = (const float*)d_in[4];
    const float* opb = (const float*)d_in[5];
    const float* w1  = (const float*)d_in[6];
    const float* b1  = (const float*)d_in[7];
    const float* lng = (const float*)d_in[8];
    const float* lnb = (const float*)d_in[9];
    const float* w2  = (const float*)d_in[10];
    const float* b2  = (const float*)d_in[11];
    const int*   par = (const int*)d_in[12];
    float* out = (float*)d_out;

    void *p_zhi, *p_zlo, *p_bch, *p_bcl, *p_bias, *p_sv;
    void *p_opwh, *p_opwl, *p_w1h, *p_w1l, *p_ohi, *p_olo, *p_jfh, *p_jfl, *p_h;
    cudaGetSymbolAddress(&p_zhi, g_zhi);  cudaGetSymbolAddress(&p_zlo, g_zlo);
    cudaGetSymbolAddress(&p_bch, g_bch);  cudaGetSymbolAddress(&p_bcl, g_bcl);
    cudaGetSymbolAddress(&p_bias, g_bias); cudaGetSymbolAddress(&p_sv, g_sv);
    cudaGetSymbolAddress(&p_opwh, g_opwh); cudaGetSymbolAddress(&p_opwl, g_opwl);
    cudaGetSymbolAddress(&p_w1h, g_w1h);   cudaGetSymbolAddress(&p_w1l, g_w1l);
    cudaGetSymbolAddress(&p_ohi, g_ohi);   cudaGetSymbolAddress(&p_olo, g_olo);
    cudaGetSymbolAddress(&p_jfh, g_jfh);   cudaGetSymbolAddress(&p_jfl, g_jfl);
    cudaGetSymbolAddress(&p_h, g_h);

    static int smem_set = 0;
    if (!smem_set) {
        cudaFuncSetAttribute(k_gemm_bf, cudaFuncAttributeMaxDynamicSharedMemorySize,
                             ST * 32768);
        smem_set = 1;
    }

    // 1) bulk splits
    k_split<<<(ROWS_Z * E_ / 4 + 255) / 256, 256>>>((const float4*)z, (uint2*)p_zhi,
                                                    (uint2*)p_zlo, ROWS_Z * E_ / 4);
    k_q<<<(J_ * E_ + 255) / 256, 256>>>(jq, ipw, ipb);
    k_sw<<<(NPAD * E_ + 255) / 256, 256>>>(ipw, ipb);
    k_split<<<(E_ * E_ / 4 + 255) / 256, 256>>>((const float4*)(ipw + (size_t)2 * E_ * E_),
        (uint2*)((__nv_bfloat16*)p_bch + NPAD * E_), (uint2*)((__nv_bfloat16*)p_bcl + NPAD * E_),
        E_ * E_ / 4);
    k_split<<<(E_ * E_ / 4 + 255) / 256, 256>>>((const float4*)opw, (uint2*)p_opwh,
                                                (uint2*)p_opwl, E_ * E_ / 4);
    k_split<<<(E_ * E_ / 4 + 255) / 256, 256>>>((const float4*)w1, (uint2*)p_w1h,
                                                (uint2*)p_w1l, E_ * E_ / 4);
    k_bcopy<<<2, 256>>>(ipb);

    // 2) merged scores|V GEMM: [131072 x 768]
    k_gemm_bf<<<dim3(NCAT / 128, ROWS_Z / 128), 256, ST * 32768>>>(
        (const __nv_bfloat16*)p_zhi, (const __nv_bfloat16*)p_zlo,
        (const __nv_bfloat16*)p_bch, (const __nv_bfloat16*)p_bcl,
        (const float*)p_bias, (float*)p_sv, nullptr, nullptr, NCAT, 0);

    // 3) softmax + o = attn @ v  (writes o as bf16 hi/lo)
    k_attn<<<dim3(B_, H_), 256>>>();

    // 4) jf = o @ out_proj^T + bo  (split output)
    k_gemm_bf<<<dim3(E_ / 128, ROWS_J / 128), 256, ST * 32768>>>(
        (const __nv_bfloat16*)p_ohi, (const __nv_bfloat16*)p_olo,
        (const __nv_bfloat16*)p_opwh, (const __nv_bfloat16*)p_opwl,
        opb, nullptr, (__nv_bfloat16*)p_jfh, (__nv_bfloat16*)p_jfl, E_, 1);

    // 5) h = jf @ w1^T + b1  (fp32 output)
    k_gemm_bf<<<dim3(E_ / 128, ROWS_J / 128), 256, ST * 32768>>>(
        (const __nv_bfloat16*)p_jfh, (const __nv_bfloat16*)p_jfl,
        (const __nv_bfloat16*)p_w1h, (const __nv_bfloat16*)p_w1l,
        b1, (float*)p_h, nullptr, nullptr, E_, 0);

    // 6) layernorm + silu
    k_ln<<<ROWS_J, 256>>>(lng, lnb);
    // 7) head projection + offsets
    k_head<<<ROWS_J / 8, 256>>>(w2, b2, out);
    // 8) forward kinematics
    k_fk<<<(B_ * 3 + 255) / 256, 256>>>(par, out);
}